// round 15
// baseline (speedup 1.0000x reference)
#include <cuda_runtime.h>
#include <cuda_fp16.h>
#include <math.h>
#include <stdint.h>

#define BB 2
#define TT 2048
#define DD 1024
#define HH 16
#define HD 64
#define MTOT (BB*TT)   // 4096
#define NW (DD*DD)

typedef unsigned long long u64;
typedef unsigned int u32;

// ---------------- scratch ----------------------------------------------------
__device__ float g_cos[TT*(HD/2)];
__device__ float g_sin[TT*(HD/2)];

__device__ __half g_Xf[MTOT*DD];
__device__ __half g_Wf[4*NW];
__device__ __half g_Cf[MTOT*DD];

__device__ __half g_Qf[BB*HH*TT*HD];   // pre-scaled by 0.125*log2(e)
__device__ __half g_Kf[BB*HH*TT*HD];
__device__ __half g_Vf[BB*HH*TT*HD];

// ---------------- fused conversions + rope table -------------------------------
__global__ __launch_bounds__(256)
void cvt_all(const float* __restrict__ x,
             const float* __restrict__ Wq, const float* __restrict__ Wk,
             const float* __restrict__ Wv, const float* __restrict__ Wo)
{
    int bid = blockIdx.x, tid = threadIdx.x;
    if (bid >= 8192) {
        int idx = (bid - 8192) * 256 + tid;
        int t = idx >> 5;
        int i = idx & 31;
        float invf = (float)exp(-((double)(2 * i) / (double)HD) * log(10000.0));
        float ang_f = (float)t * invf;
        double ang = (double)ang_f;
        g_cos[idx] = (float)cos(ang);
        g_sin[idx] = (float)sin(ang);
        return;
    }
    const float* src;
    __half* dst;
    int i;
    if (bid < 4096) {
        src = x; dst = g_Xf;
        i = (bid * 256 + tid) * 4;
    } else {
        int slot = (bid - 4096) >> 10;
        src = (slot == 0) ? Wq : (slot == 1) ? Wk : (slot == 2) ? Wv : Wo;
        dst = g_Wf + (size_t)slot * NW;
        i = (((bid - 4096) & 1023) * 256 + tid) * 4;
    }
    float4 v = *(const float4*)(src + i);
    __half f0 = __float2half_rn(v.x), f1 = __float2half_rn(v.y);
    __half f2 = __float2half_rn(v.z), f3 = __float2half_rn(v.w);
    uint2 fh;
    fh.x = ((u32)__half_as_ushort(f1) << 16) | __half_as_ushort(f0);
    fh.y = ((u32)__half_as_ushort(f3) << 16) | __half_as_ushort(f2);
    *(uint2*)(dst + i) = fh;
}

// ---------------- mma.sync helpers ---------------------------------------------
__device__ __forceinline__ u32 smem_u32(const void* p) {
    u32 a;
    asm("{ .reg .u64 t; cvta.to.shared.u64 t, %1; cvt.u32.u64 %0, t; }"
        : "=r"(a) : "l"(p));
    return a;
}
__device__ __forceinline__ void ldsm4(u32* r, u32 addr) {
    asm volatile("ldmatrix.sync.aligned.m8n8.x4.shared.b16 {%0,%1,%2,%3}, [%4];"
        : "=r"(r[0]), "=r"(r[1]), "=r"(r[2]), "=r"(r[3]) : "r"(addr));
}
__device__ __forceinline__ void ldsm4t(u32* r, u32 addr) {
    asm volatile("ldmatrix.sync.aligned.m8n8.x4.trans.shared.b16 {%0,%1,%2,%3}, [%4];"
        : "=r"(r[0]), "=r"(r[1]), "=r"(r[2]), "=r"(r[3]) : "r"(addr));
}
__device__ __forceinline__ void mma16816f(float* c, const u32* a, const u32* b) {
    asm volatile(
        "mma.sync.aligned.m16n8k16.row.col.f32.f16.f16.f32 "
        "{%0,%1,%2,%3}, {%4,%5,%6,%7}, {%8,%9}, {%0,%1,%2,%3};"
        : "+f"(c[0]), "+f"(c[1]), "+f"(c[2]), "+f"(c[3])
        : "r"(a[0]), "r"(a[1]), "r"(a[2]), "r"(a[3]), "r"(b[0]), "r"(b[1]));
}
__device__ __forceinline__ void cp16(u32 dst, const void* src) {
    asm volatile("cp.async.ca.shared.global [%0], [%1], 16;"
                 :: "r"(dst), "l"(src));
}
__device__ __forceinline__ void cp_commit() {
    asm volatile("cp.async.commit_group;" ::: "memory");
}
__device__ __forceinline__ u32 packf16(float a, float b) {
    __half ha = __float2half_rn(a), hb = __float2half_rn(b);
    return ((u32)__half_as_ushort(hb) << 16) | __half_as_ushort(ha);
}
__device__ __forceinline__ float ex2(float x) {
    float r; asm("ex2.approx.f32 %0, %1;" : "=f"(r) : "f"(x)); return r;
}

#define TPITCH 72
#define TBYTES (128*TPITCH*2)
#define BUF2 (2*TBYTES)

// ---------------- fp16 GEMM mainloop: depth-3, issue-after-compute ---------------
__device__ __forceinline__ void mma_mainloop_f16s(
    const __half* __restrict__ A, const __half* __restrict__ B,
    int m0, int n0, u32 sb, float acc[2][8][4])
{
    const int tid = threadIdx.x;
    const int lane = tid & 31;
    const int wid = tid >> 5;
    const int wm = wid & 3;
    const int wn = wid >> 2;

    int lrow[4], lcol[4];
    #pragma unroll
    for (int it = 0; it < 4; it++) {
        int flat = it * 2048 + tid * 8;
        lrow[it] = flat >> 6;
        lcol[it] = flat & 63;
    }

    const int NCHUNK = DD / 64;

    #define ISSUE2(kc_, buf_) do {                                             \
        if ((kc_) < NCHUNK) {                                                  \
            int kb_ = (kc_) * 64;                                              \
            _Pragma("unroll")                                                  \
            for (int it = 0; it < 4; it++) {                                   \
                size_t ao_ = (size_t)(m0 + lrow[it]) * DD + kb_ + lcol[it];    \
                size_t bo_ = (size_t)(n0 + lrow[it]) * DD + kb_ + lcol[it];    \
                u32 so_ = sb + (buf_) * BUF2 + lrow[it] * (TPITCH*2)           \
                          + lcol[it] * 2;                                      \
                cp16(so_ + 0 * TBYTES, A + ao_);                               \
                cp16(so_ + 1 * TBYTES, B + bo_);                               \
            }                                                                  \
        }                                                                      \
        cp_commit();                                                           \
    } while (0)

    ISSUE2(0, 0);
    ISSUE2(1, 1);
    ISSUE2(2, 2);

    const int arow = lane & 15;
    const int kaddA = (lane >= 16) ? 16 : 0;
    const int brow = (lane & 7) + ((lane >> 4) << 3);
    const int kaddB = ((lane >> 3) & 1) * 16;

    const u32 aoff0 = (u32)((wm * 32 + arow) * (TPITCH*2) + kaddA);
    const u32 boff0 = (u32)((wn * 64 + brow) * (TPITCH*2) + kaddB);

    #pragma unroll
    for (int mt = 0; mt < 2; mt++)
        #pragma unroll
        for (int nt = 0; nt < 8; nt++)
            #pragma unroll
            for (int e = 0; e < 4; e++) acc[mt][nt][e] = 0.0f;

    int buf = 0;
    for (int kc = 0; kc < NCHUNK; kc++) {
        asm volatile("cp.async.wait_group 2;" ::: "memory");
        __syncthreads();
        const u32 base = sb + buf * BUF2;

        #pragma unroll
        for (int kk = 0; kk < 4; kk++) {
            u32 ah[2][4], bfr[4][4];
            #pragma unroll
            for (int mt = 0; mt < 2; mt++) {
                u32 a_addr = base + aoff0 + mt * (16 * TPITCH * 2) + kk * 32;
                ldsm4(ah[mt], a_addr);
            }
            #pragma unroll
            for (int p = 0; p < 4; p++) {
                u32 b_addr = base + boff0 + p * (16 * TPITCH * 2) + kk * 32;
                ldsm4(bfr[p], b_addr + TBYTES);
            }
            #pragma unroll
            for (int mt = 0; mt < 2; mt++) {
                #pragma unroll
                for (int nt = 0; nt < 8; nt++) {
                    const u32* bp = &bfr[nt >> 1][(nt & 1) * 2];
                    mma16816f(acc[mt][nt], ah[mt], bp);
                }
            }
        }
        __syncthreads();
        // refill the just-consumed buffer with chunk kc+3
        ISSUE2(kc + 3, buf);
        buf = (buf == 2) ? 0 : buf + 1;
    }
    #undef ISSUE2

    asm volatile("cp.async.wait_group 0;" ::: "memory");
}

// ---------------- fused QKV GEMM ---------------------------------------------------
__global__ __launch_bounds__(256, 2)
void qkv_mma(const float* __restrict__ bq, const float* __restrict__ bk,
             const float* __restrict__ bv)
{
    extern __shared__ __align__(16) char smem[];
    const u32 sb = smem_u32(smem);
    const int wsel = blockIdx.x >> 3;
    const int n0 = (blockIdx.x & 7) * 128;
    const int m0 = blockIdx.y * 128;

    float acc[2][8][4];
    mma_mainloop_f16s(g_Xf, g_Wf + (size_t)wsel * NW, m0, n0, sb, acc);

    const int lane = threadIdx.x & 31;
    const int wid = threadIdx.x >> 5;
    const int wm = wid & 3;
    const int wn = wid >> 2;
    const int group = lane >> 2;
    const int lc2 = (lane & 3) * 2;

    const int nb0 = n0 + wn * 64;
    const int hsel = nb0 >> 6;
    const float* bias = (wsel == 0) ? bq : (wsel == 1) ? bk : bv;

    if (wsel < 2) {
        __half* dOut = (wsel == 0) ? g_Qf : g_Kf;
        const float scale = (wsel == 0) ? 0.125f * 1.4426950408889634f : 1.0f;
        float bA0[4], bA1[4], bB0[4], bB1[4];
        #pragma unroll
        for (int nt = 0; nt < 4; nt++) {
            int nl = nb0 + nt * 8 + lc2;
            bA0[nt] = bias[nl];      bA1[nt] = bias[nl + 1];
            bB0[nt] = bias[nl + 32]; bB1[nt] = bias[nl + 33];
        }
        #pragma unroll
        for (int mt = 0; mt < 2; mt++) {
            #pragma unroll
            for (int e01 = 0; e01 < 2; e01++) {
                int rr = m0 + wm * 32 + mt * 16 + group + e01 * 8;
                int bi = rr >> 11;
                int t = rr & (TT - 1);
                size_t ob = ((size_t)(bi * HH + hsel) * TT + t) * HD;
                #pragma unroll
                for (int nt = 0; nt < 4; nt++) {
                    int d = nt * 8 + lc2;
                    float2 cc = *(const float2*)&g_cos[t * 32 + d];
                    float2 ssv = *(const float2*)&g_sin[t * 32 + d];
                    float va0 = acc[mt][nt][2 * e01]     + bA0[nt];
                    float va1 = acc[mt][nt][2 * e01 + 1] + bA1[nt];
                    float vb0 = acc[mt][nt + 4][2 * e01]     + bB0[nt];
                    float vb1 = acc[mt][nt + 4][2 * e01 + 1] + bB1[nt];
                    float o0 = (va0 * cc.x - vb0 * ssv.x) * scale;
                    float o1 = (va1 * cc.y - vb1 * ssv.y) * scale;
                    float p0 = (va0 * ssv.x + vb0 * cc.x) * scale;
                    float p1 = (va1 * ssv.y + vb1 * cc.y) * scale;
                    *(u32*)(dOut + ob + d)      = packf16(o0, o1);
                    *(u32*)(dOut + ob + d + 32) = packf16(p0, p1);
                }
            }
        }
    } else {
        float b0v[8], b1v[8];
        #pragma unroll
        for (int nt = 0; nt < 8; nt++) {
            int nl = nb0 + nt * 8 + lc2;
            b0v[nt] = bias[nl]; b1v[nt] = bias[nl + 1];
        }
        #pragma unroll
        for (int mt = 0; mt < 2; mt++) {
            #pragma unroll
            for (int e01 = 0; e01 < 2; e01++) {
                int rr = m0 + wm * 32 + mt * 16 + group + e01 * 8;
                int bi = rr >> 11;
                int t = rr & (TT - 1);
                size_t ob = ((size_t)(bi * HH + hsel) * TT + t) * HD;
                #pragma unroll
                for (int nt = 0; nt < 8; nt++) {
                    int d = nt * 8 + lc2;
                    float v0 = acc[mt][nt][2 * e01]     + b0v[nt];
                    float v1 = acc[mt][nt][2 * e01 + 1] + b1v[nt];
                    *(u32*)(g_Vf + ob + d) = packf16(v0, v1);
                }
            }
        }
    }
}

// ---------------- output projection (fp16 single-term, fp32 out) ------------------
__global__ __launch_bounds__(256, 2)
void out_mma(const float* __restrict__ bias, float* __restrict__ dst)
{
    extern __shared__ __align__(16) char smem[];
    const u32 sb = smem_u32(smem);
    const int m0 = blockIdx.y * 128;
    const int n0 = blockIdx.x * 128;

    float acc[2][8][4];
    mma_mainloop_f16s(g_Cf, g_Wf + 3ull * NW, m0, n0, sb, acc);

    const int lane = threadIdx.x & 31;
    const int wid = threadIdx.x >> 5;
    const int wm = wid & 3;
    const int wn = wid >> 2;
    const int group = lane >> 2;
    const int lc2 = (lane & 3) * 2;

    #pragma unroll
    for (int mt = 0; mt < 2; mt++) {
        #pragma unroll
        for (int nt = 0; nt < 8; nt++) {
            int r = m0 + wm * 32 + mt * 16 + group;
            int c = n0 + wn * 64 + nt * 8 + lc2;
            float b0 = bias[c], b1 = bias[c + 1];
            float2 v01 = make_float2(acc[mt][nt][0] + b0, acc[mt][nt][1] + b1);
            float2 v23 = make_float2(acc[mt][nt][2] + b0, acc[mt][nt][3] + b1);
            *(float2*)&dst[(size_t)r * DD + c] = v01;
            *(float2*)&dst[(size_t)(r + 8) * DD + c] = v23;
        }
    }
}

// ---------------- tensor-core flash attention: paired q-tiles ----------------------
#define APITCH 144
#define ATILE 9216
#define ABUF  (2*ATILE)            // Kf, Vf
#define QSOFF (3*ABUF)             // 55296
#define ASMEM (QSOFF + 18432)      // 73728

__global__ __launch_bounds__(256, 2)
void attn_mma()
{
    extern __shared__ __align__(16) char smem[];
    const u32 sb = smem_u32(smem);
    const int tid = threadIdx.x;
    const int lane = tid & 31;
    const int w = tid >> 5;
    const int bh = blockIdx.z * HH + blockIdx.y;
    const int b = blockIdx.z, h = blockIdx.y;

    const int arow = lane & 15;
    const int kaddA = (lane >= 16) ? 16 : 0;
    const int brow = (lane & 7) + ((lane >> 4) << 3);
    const int kaddB = ((lane >> 3) & 1) * 16;
    const int vtr = lane & 15;
    const int vtc = (lane >> 4) << 3;
    const int g = lane >> 2;
    const int colq = 2 * (lane & 3);
    const u32 ones2[2] = {0x3C003C00u, 0x3C003C00u};

    #pragma unroll 1
    for (int seg = 0; seg < 2; seg++) {
        const int qt = seg == 0 ? (int)(15 - blockIdx.x) : (int)blockIdx.x;
        const int q0 = qt * 128;
        const int nkt = 2 * qt + 2;

        {
            size_t qg = ((size_t)bh * TT + q0) * HD;
            #pragma unroll
            for (int it = 0; it < 4; it++) {
                int ci = it * 256 + tid;
                int row = ci >> 3, ce = (ci & 7) * 8;
                cp16(sb + QSOFF + row * APITCH + ce * 2,
                     g_Qf + qg + (size_t)row * HD + ce);
            }
            cp_commit();
        }

        #define ISSUEKV(kt_, buf_) do {                                       \
            if ((kt_) < nkt) {                                                 \
                _Pragma("unroll")                                              \
                for (int rep = 0; rep < 2; rep++) {                            \
                    int ci = rep * 256 + tid;                                  \
                    int row = ci >> 3, ce = (ci & 7) * 8;                      \
                    size_t kg = ((size_t)bh * TT + (kt_) * 64 + row) * HD + ce;\
                    u32 s0 = sb + (buf_) * ABUF + row * APITCH + ce * 2;       \
                    cp16(s0,         g_Kf + kg);                               \
                    cp16(s0 + ATILE, g_Vf + kg);                               \
                }                                                              \
            }                                                                  \
            cp_commit();                                                       \
        } while (0)

        ISSUEKV(0, 0);
        ISSUEKV(1, 1);

        asm volatile("cp.async.wait_group 2;" ::: "memory");
        __syncthreads();

        u32 qh[4][4];
        #pragma unroll
        for (int kk = 0; kk < 4; kk++) {
            u32 aaddr = sb + QSOFF + (w * 16 + arow) * APITCH + kaddA + kk * 32;
            ldsm4(qh[kk], aaddr);
        }

        float o[8][4];
        #pragma unroll
        for (int nt = 0; nt < 8; nt++)
            #pragma unroll
            for (int e = 0; e < 4; e++) o[nt][e] = 0.0f;
        float acc_l[4] = {0.0f, 0.0f, 0.0f, 0.0f};

        const int rowg0 = q0 + w * 16 + g;
        const int rowg1 = rowg0 + 8;

        int buf = 0;
        int nbuf = 2;
        for (int kt = 0; kt < nkt; kt++) {
            asm volatile("cp.async.wait_group 1;" ::: "memory");
            __syncthreads();
            ISSUEKV(kt + 2, nbuf);

            const u32 kbase = sb + buf * ABUF;

            float s[8][4];
            #pragma unroll
            for (int nt = 0; nt < 8; nt++)
                #pragma unroll
                for (int e = 0; e < 4; e++) s[nt][e] = 0.0f;

            #pragma unroll
            for (int kk = 0; kk < 4; kk++) {
                #pragma unroll
                for (int p = 0; p < 4; p++) {
                    u32 kh[4];
                    u32 baddr = kbase + (p * 16 + brow) * APITCH + kaddB + kk * 32;
                    ldsm4(kh, baddr);
                    int nt0 = 2 * p;
                    mma16816f(s[nt0], qh[kk], &kh[0]);
                    mma16816f(s[nt0 + 1], qh[kk], &kh[2]);
                }
            }

            if (kt >= 2 * qt) {
                int kc0 = kt * 64;
                #pragma unroll
                for (int nt = 0; nt < 8; nt++) {
                    int c = kc0 + nt * 8 + colq;
                    if (c     > rowg0) s[nt][0] = -30000.0f;
                    if (c + 1 > rowg0) s[nt][1] = -30000.0f;
                    if (c     > rowg1) s[nt][2] = -30000.0f;
                    if (c + 1 > rowg1) s[nt][3] = -30000.0f;
                }
            }

            #pragma unroll
            for (int kk = 0; kk < 4; kk++) {
                u32 ph[4];
                ph[0] = packf16(ex2(s[2*kk][0]),   ex2(s[2*kk][1]));
                ph[1] = packf16(ex2(s[2*kk][2]),   ex2(s[2*kk][3]));
                ph[2] = packf16(ex2(s[2*kk+1][0]), ex2(s[2*kk+1][1]));
                ph[3] = packf16(ex2(s[2*kk+1][2]), ex2(s[2*kk+1][3]));
                mma16816f(acc_l, ph, ones2);
                #pragma unroll
                for (int pp = 0; pp < 4; pp++) {
                    u32 vh[4];
                    u32 vaddr = kbase + ATILE + (kk * 16 + vtr) * APITCH
                                + (pp * 16 + vtc) * 2;
                    ldsm4t(vh, vaddr);
                    int nt0 = 2 * pp;
                    mma16816f(o[nt0], ph, &vh[0]);
                    mma16816f(o[nt0 + 1], ph, &vh[2]);
                }
            }

            buf = (buf == 2) ? 0 : buf + 1;
            nbuf = (nbuf == 2) ? 0 : nbuf + 1;
        }
        #undef ISSUEKV

        float il0 = 1.0f / acc_l[0];
        float il1 = 1.0f / acc_l[2];
        #pragma unroll
        for (int nt = 0; nt < 8; nt++) {
            int col = h * HD + nt * 8 + colq;
            size_t o0 = ((size_t)b * TT + rowg0) * DD + col;
            size_t o1 = ((size_t)b * TT + rowg1) * DD + col;
            *(u32*)(g_Cf + o0) = packf16(o[nt][0] * il0, o[nt][1] * il0);
            *(u32*)(g_Cf + o1) = packf16(o[nt][2] * il1, o[nt][3] * il1);
        }

        asm volatile("cp.async.wait_group 0;" ::: "memory");
        __syncthreads();
    }
}

// ---------------- launch -------------------------------------------------------------
extern "C" void kernel_launch(void* const* d_in, const int* in_sizes, int n_in,
                              void* d_out, int out_size)
{
    const float* x  = (const float*)d_in[0];
    const float* Wq = (const float*)d_in[2];
    const float* bq = (const float*)d_in[3];
    const float* Wk = (const float*)d_in[4];
    const float* bk = (const float*)d_in[5];
    const float* Wv = (const float*)d_in[6];
    const float* bv = (const float*)d_in[7];
    const float* Wo = (const float*)d_in[8];
    const float* bo = (const float*)d_in[9];
    float* out = (float*)d_out;

    cvt_all<<<8448, 256>>>(x, Wq, Wk, Wv, Wo);

    cudaFuncSetAttribute(qkv_mma, cudaFuncAttributeMaxDynamicSharedMemorySize,
                         3 * BUF2);
    cudaFuncSetAttribute(out_mma, cudaFuncAttributeMaxDynamicSharedMemorySize,
                         3 * BUF2);
    cudaFuncSetAttribute(attn_mma, cudaFuncAttributeMaxDynamicSharedMemorySize,
                         ASMEM);

    dim3 qgrid(24, MTOT / 128);
    qkv_mma<<<qgrid, 256, 3 * BUF2>>>(bq, bk, bv);

    dim3 agrid(8, HH, BB);
    attn_mma<<<agrid, 256, ASMEM>>>();

    dim3 ogrid(DD / 128, MTOT / 128);
    out_mma<<<ogrid, 256, 3 * BUF2>>>(bo, out);
}

// round 16
// speedup vs baseline: 1.0599x; 1.0599x over previous
#include <cuda_runtime.h>
#include <cuda_fp16.h>
#include <math.h>
#include <stdint.h>

#define BB 2
#define TT 2048
#define DD 1024
#define HH 16
#define HD 64
#define MTOT (BB*TT)   // 4096
#define NW (DD*DD)

typedef unsigned long long u64;
typedef unsigned int u32;

// ---------------- scratch ----------------------------------------------------
__device__ float g_cos[TT*(HD/2)];
__device__ float g_sin[TT*(HD/2)];

__device__ __half g_Xf[MTOT*DD];
__device__ __half g_Wf[4*NW];
__device__ __half g_Cf[MTOT*DD];

__device__ __half g_Qf[BB*HH*TT*HD];   // pre-scaled by 0.125*log2(e)
__device__ __half g_Kf[BB*HH*TT*HD];
__device__ __half g_Vf[BB*HH*TT*HD];

// ---------------- fused conversions + rope table -------------------------------
__global__ __launch_bounds__(256)
void cvt_all(const float* __restrict__ x,
             const float* __restrict__ Wq, const float* __restrict__ Wk,
             const float* __restrict__ Wv, const float* __restrict__ Wo)
{
    int bid = blockIdx.x, tid = threadIdx.x;
    if (bid >= 8192) {
        int idx = (bid - 8192) * 256 + tid;
        int t = idx >> 5;
        int i = idx & 31;
        float invf = (float)exp(-((double)(2 * i) / (double)HD) * log(10000.0));
        float ang_f = (float)t * invf;
        double ang = (double)ang_f;
        g_cos[idx] = (float)cos(ang);
        g_sin[idx] = (float)sin(ang);
        return;
    }
    const float* src;
    __half* dst;
    int i;
    if (bid < 4096) {
        src = x; dst = g_Xf;
        i = (bid * 256 + tid) * 4;
    } else {
        int slot = (bid - 4096) >> 10;
        src = (slot == 0) ? Wq : (slot == 1) ? Wk : (slot == 2) ? Wv : Wo;
        dst = g_Wf + (size_t)slot * NW;
        i = (((bid - 4096) & 1023) * 256 + tid) * 4;
    }
    float4 v = *(const float4*)(src + i);
    __half f0 = __float2half_rn(v.x), f1 = __float2half_rn(v.y);
    __half f2 = __float2half_rn(v.z), f3 = __float2half_rn(v.w);
    uint2 fh;
    fh.x = ((u32)__half_as_ushort(f1) << 16) | __half_as_ushort(f0);
    fh.y = ((u32)__half_as_ushort(f3) << 16) | __half_as_ushort(f2);
    *(uint2*)(dst + i) = fh;
}

// ---------------- mma.sync helpers ---------------------------------------------
__device__ __forceinline__ u32 smem_u32(const void* p) {
    u32 a;
    asm("{ .reg .u64 t; cvta.to.shared.u64 t, %1; cvt.u32.u64 %0, t; }"
        : "=r"(a) : "l"(p));
    return a;
}
__device__ __forceinline__ void ldsm4(u32* r, u32 addr) {
    asm volatile("ldmatrix.sync.aligned.m8n8.x4.shared.b16 {%0,%1,%2,%3}, [%4];"
        : "=r"(r[0]), "=r"(r[1]), "=r"(r[2]), "=r"(r[3]) : "r"(addr));
}
__device__ __forceinline__ void ldsm4t(u32* r, u32 addr) {
    asm volatile("ldmatrix.sync.aligned.m8n8.x4.trans.shared.b16 {%0,%1,%2,%3}, [%4];"
        : "=r"(r[0]), "=r"(r[1]), "=r"(r[2]), "=r"(r[3]) : "r"(addr));
}
__device__ __forceinline__ void mma16816f(float* c, const u32* a, const u32* b) {
    asm volatile(
        "mma.sync.aligned.m16n8k16.row.col.f32.f16.f16.f32 "
        "{%0,%1,%2,%3}, {%4,%5,%6,%7}, {%8,%9}, {%0,%1,%2,%3};"
        : "+f"(c[0]), "+f"(c[1]), "+f"(c[2]), "+f"(c[3])
        : "r"(a[0]), "r"(a[1]), "r"(a[2]), "r"(a[3]), "r"(b[0]), "r"(b[1]));
}
__device__ __forceinline__ void cp16(u32 dst, const void* src) {
    asm volatile("cp.async.cg.shared.global [%0], [%1], 16;"
                 :: "r"(dst), "l"(src));
}
__device__ __forceinline__ void cp_commit() {
    asm volatile("cp.async.commit_group;" ::: "memory");
}
__device__ __forceinline__ u32 packf16(float a, float b) {
    __half ha = __float2half_rn(a), hb = __float2half_rn(b);
    return ((u32)__half_as_ushort(hb) << 16) | __half_as_ushort(ha);
}
__device__ __forceinline__ float ex2(float x) {
    float r; asm("ex2.approx.f32 %0, %1;" : "=f"(r) : "f"(x)); return r;
}

#define TPITCH 72
#define TBYTES (128*TPITCH*2)
#define BUF2 (2*TBYTES)

// ---------------- fp16 GEMM mainloop: depth-2, issue-after-compute (champion) ----
__device__ __forceinline__ void mma_mainloop_f16s(
    const __half* __restrict__ A, const __half* __restrict__ B,
    int m0, int n0, u32 sb, float acc[2][8][4])
{
    const int tid = threadIdx.x;
    const int lane = tid & 31;
    const int wid = tid >> 5;
    const int wm = wid & 3;
    const int wn = wid >> 2;

    int lrow[4], lcol[4];
    #pragma unroll
    for (int it = 0; it < 4; it++) {
        int flat = it * 2048 + tid * 8;
        lrow[it] = flat >> 6;
        lcol[it] = flat & 63;
    }

    #define ISSUE2(kc_, buf_) do {                                             \
        int kb_ = (kc_) * 64;                                                  \
        _Pragma("unroll")                                                      \
        for (int it = 0; it < 4; it++) {                                       \
            size_t ao_ = (size_t)(m0 + lrow[it]) * DD + kb_ + lcol[it];        \
            size_t bo_ = (size_t)(n0 + lrow[it]) * DD + kb_ + lcol[it];        \
            u32 so_ = sb + (buf_) * BUF2 + lrow[it] * (TPITCH*2)               \
                      + lcol[it] * 2;                                          \
            cp16(so_ + 0 * TBYTES, A + ao_);                                   \
            cp16(so_ + 1 * TBYTES, B + bo_);                                   \
        }                                                                      \
    } while (0)

    ISSUE2(0, 0); cp_commit();
    ISSUE2(1, 1); cp_commit();

    const int arow = lane & 15;
    const int kaddA = (lane >= 16) ? 16 : 0;
    const int brow = (lane & 7) + ((lane >> 4) << 3);
    const int kaddB = ((lane >> 3) & 1) * 16;

    const u32 aoff0 = (u32)((wm * 32 + arow) * (TPITCH*2) + kaddA);
    const u32 boff0 = (u32)((wn * 64 + brow) * (TPITCH*2) + kaddB);

    #pragma unroll
    for (int mt = 0; mt < 2; mt++)
        #pragma unroll
        for (int nt = 0; nt < 8; nt++)
            #pragma unroll
            for (int e = 0; e < 4; e++) acc[mt][nt][e] = 0.0f;

    const int NCHUNK = DD / 64;

    for (int kc = 0; kc < NCHUNK; kc++) {
        asm volatile("cp.async.wait_group 1;" ::: "memory");
        __syncthreads();
        const u32 base = sb + (kc & 1) * BUF2;

        #pragma unroll
        for (int kk = 0; kk < 4; kk++) {
            u32 ah[2][4], bfr[4][4];
            #pragma unroll
            for (int mt = 0; mt < 2; mt++) {
                u32 a_addr = base + aoff0 + mt * (16 * TPITCH * 2) + kk * 32;
                ldsm4(ah[mt], a_addr);
            }
            #pragma unroll
            for (int p = 0; p < 4; p++) {
                u32 b_addr = base + boff0 + p * (16 * TPITCH * 2) + kk * 32;
                ldsm4(bfr[p], b_addr + TBYTES);
            }
            #pragma unroll
            for (int mt = 0; mt < 2; mt++) {
                #pragma unroll
                for (int nt = 0; nt < 8; nt++) {
                    const u32* bp = &bfr[nt >> 1][(nt & 1) * 2];
                    mma16816f(acc[mt][nt], ah[mt], bp);
                }
            }
        }
        __syncthreads();
        if (kc + 2 < NCHUNK) ISSUE2(kc + 2, kc & 1);
        cp_commit();
    }
    #undef ISSUE2
}

// ---------------- fused QKV GEMM ---------------------------------------------------
__global__ __launch_bounds__(256, 2)
void qkv_mma(const float* __restrict__ bq, const float* __restrict__ bk,
             const float* __restrict__ bv)
{
    extern __shared__ __align__(16) char smem[];
    const u32 sb = smem_u32(smem);
    const int wsel = blockIdx.x >> 3;
    const int n0 = (blockIdx.x & 7) * 128;
    const int m0 = blockIdx.y * 128;

    float acc[2][8][4];
    mma_mainloop_f16s(g_Xf, g_Wf + (size_t)wsel * NW, m0, n0, sb, acc);

    const int lane = threadIdx.x & 31;
    const int wid = threadIdx.x >> 5;
    const int wm = wid & 3;
    const int wn = wid >> 2;
    const int group = lane >> 2;
    const int lc2 = (lane & 3) * 2;

    const int nb0 = n0 + wn * 64;
    const int hsel = nb0 >> 6;
    const float* bias = (wsel == 0) ? bq : (wsel == 1) ? bk : bv;

    if (wsel < 2) {
        __half* dOut = (wsel == 0) ? g_Qf : g_Kf;
        const float scale = (wsel == 0) ? 0.125f * 1.4426950408889634f : 1.0f;
        float bA0[4], bA1[4], bB0[4], bB1[4];
        #pragma unroll
        for (int nt = 0; nt < 4; nt++) {
            int nl = nb0 + nt * 8 + lc2;
            bA0[nt] = bias[nl];      bA1[nt] = bias[nl + 1];
            bB0[nt] = bias[nl + 32]; bB1[nt] = bias[nl + 33];
        }
        #pragma unroll
        for (int mt = 0; mt < 2; mt++) {
            #pragma unroll
            for (int e01 = 0; e01 < 2; e01++) {
                int rr = m0 + wm * 32 + mt * 16 + group + e01 * 8;
                int bi = rr >> 11;
                int t = rr & (TT - 1);
                size_t ob = ((size_t)(bi * HH + hsel) * TT + t) * HD;
                #pragma unroll
                for (int nt = 0; nt < 4; nt++) {
                    int d = nt * 8 + lc2;
                    float2 cc = *(const float2*)&g_cos[t * 32 + d];
                    float2 ssv = *(const float2*)&g_sin[t * 32 + d];
                    float va0 = acc[mt][nt][2 * e01]     + bA0[nt];
                    float va1 = acc[mt][nt][2 * e01 + 1] + bA1[nt];
                    float vb0 = acc[mt][nt + 4][2 * e01]     + bB0[nt];
                    float vb1 = acc[mt][nt + 4][2 * e01 + 1] + bB1[nt];
                    float o0 = (va0 * cc.x - vb0 * ssv.x) * scale;
                    float o1 = (va1 * cc.y - vb1 * ssv.y) * scale;
                    float p0 = (va0 * ssv.x + vb0 * cc.x) * scale;
                    float p1 = (va1 * ssv.y + vb1 * cc.y) * scale;
                    *(u32*)(dOut + ob + d)      = packf16(o0, o1);
                    *(u32*)(dOut + ob + d + 32) = packf16(p0, p1);
                }
            }
        }
    } else {
        float b0v[8], b1v[8];
        #pragma unroll
        for (int nt = 0; nt < 8; nt++) {
            int nl = nb0 + nt * 8 + lc2;
            b0v[nt] = bias[nl]; b1v[nt] = bias[nl + 1];
        }
        #pragma unroll
        for (int mt = 0; mt < 2; mt++) {
            #pragma unroll
            for (int e01 = 0; e01 < 2; e01++) {
                int rr = m0 + wm * 32 + mt * 16 + group + e01 * 8;
                int bi = rr >> 11;
                int t = rr & (TT - 1);
                size_t ob = ((size_t)(bi * HH + hsel) * TT + t) * HD;
                #pragma unroll
                for (int nt = 0; nt < 8; nt++) {
                    int d = nt * 8 + lc2;
                    float v0 = acc[mt][nt][2 * e01]     + b0v[nt];
                    float v1 = acc[mt][nt][2 * e01 + 1] + b1v[nt];
                    *(u32*)(g_Vf + ob + d) = packf16(v0, v1);
                }
            }
        }
    }
}

// ---------------- output projection (fp16 single-term, fp32 out) ------------------
__global__ __launch_bounds__(256, 2)
void out_mma(const float* __restrict__ bias, float* __restrict__ dst)
{
    extern __shared__ __align__(16) char smem[];
    const u32 sb = smem_u32(smem);
    const int m0 = blockIdx.y * 128;
    const int n0 = blockIdx.x * 128;

    float acc[2][8][4];
    mma_mainloop_f16s(g_Cf, g_Wf + 3ull * NW, m0, n0, sb, acc);

    const int lane = threadIdx.x & 31;
    const int wid = threadIdx.x >> 5;
    const int wm = wid & 3;
    const int wn = wid >> 2;
    const int group = lane >> 2;
    const int lc2 = (lane & 3) * 2;

    #pragma unroll
    for (int mt = 0; mt < 2; mt++) {
        #pragma unroll
        for (int nt = 0; nt < 8; nt++) {
            int r = m0 + wm * 32 + mt * 16 + group;
            int c = n0 + wn * 64 + nt * 8 + lc2;
            float b0 = bias[c], b1 = bias[c + 1];
            float2 v01 = make_float2(acc[mt][nt][0] + b0, acc[mt][nt][1] + b1);
            float2 v23 = make_float2(acc[mt][nt][2] + b0, acc[mt][nt][3] + b1);
            *(float2*)&dst[(size_t)r * DD + c] = v01;
            *(float2*)&dst[(size_t)(r + 8) * DD + c] = v23;
        }
    }
}

// ---------------- tensor-core flash attention: paired q-tiles ----------------------
#define APITCH 144
#define ATILE 9216
#define ABUF  (2*ATILE)            // Kf, Vf
#define QSOFF (3*ABUF)             // 55296
#define ASMEM (QSOFF + 18432)      // 73728

__global__ __launch_bounds__(256, 2)
void attn_mma()
{
    extern __shared__ __align__(16) char smem[];
    const u32 sb = smem_u32(smem);
    const int tid = threadIdx.x;
    const int lane = tid & 31;
    const int w = tid >> 5;
    const int bh = blockIdx.z * HH + blockIdx.y;
    const int b = blockIdx.z, h = blockIdx.y;

    const int arow = lane & 15;
    const int kaddA = (lane >= 16) ? 16 : 0;
    const int brow = (lane & 7) + ((lane >> 4) << 3);
    const int kaddB = ((lane >> 3) & 1) * 16;
    const int vtr = lane & 15;
    const int vtc = (lane >> 4) << 3;
    const int g = lane >> 2;
    const int colq = 2 * (lane & 3);
    const u32 ones2[2] = {0x3C003C00u, 0x3C003C00u};

    #pragma unroll 1
    for (int seg = 0; seg < 2; seg++) {
        const int qt = seg == 0 ? (int)(15 - blockIdx.x) : (int)blockIdx.x;
        const int q0 = qt * 128;
        const int nkt = 2 * qt + 2;

        {
            size_t qg = ((size_t)bh * TT + q0) * HD;
            #pragma unroll
            for (int it = 0; it < 4; it++) {
                int ci = it * 256 + tid;
                int row = ci >> 3, ce = (ci & 7) * 8;
                cp16(sb + QSOFF + row * APITCH + ce * 2,
                     g_Qf + qg + (size_t)row * HD + ce);
            }
            cp_commit();
        }

        #define ISSUEKV(kt_, buf_) do {                                       \
            if ((kt_) < nkt) {                                                 \
                _Pragma("unroll")                                              \
                for (int rep = 0; rep < 2; rep++) {                            \
                    int ci = rep * 256 + tid;                                  \
                    int row = ci >> 3, ce = (ci & 7) * 8;                      \
                    size_t kg = ((size_t)bh * TT + (kt_) * 64 + row) * HD + ce;\
                    u32 s0 = sb + (buf_) * ABUF + row * APITCH + ce * 2;       \
                    cp16(s0,         g_Kf + kg);                               \
                    cp16(s0 + ATILE, g_Vf + kg);                               \
                }                                                              \
            }                                                                  \
            cp_commit();                                                       \
        } while (0)

        ISSUEKV(0, 0);
        ISSUEKV(1, 1);

        asm volatile("cp.async.wait_group 2;" ::: "memory");
        __syncthreads();

        u32 qh[4][4];
        #pragma unroll
        for (int kk = 0; kk < 4; kk++) {
            u32 aaddr = sb + QSOFF + (w * 16 + arow) * APITCH + kaddA + kk * 32;
            ldsm4(qh[kk], aaddr);
        }

        float o[8][4];
        #pragma unroll
        for (int nt = 0; nt < 8; nt++)
            #pragma unroll
            for (int e = 0; e < 4; e++) o[nt][e] = 0.0f;
        float acc_l[4] = {0.0f, 0.0f, 0.0f, 0.0f};

        const int rowg0 = q0 + w * 16 + g;
        const int rowg1 = rowg0 + 8;

        int buf = 0;
        int nbuf = 2;
        for (int kt = 0; kt < nkt; kt++) {
            asm volatile("cp.async.wait_group 1;" ::: "memory");
            __syncthreads();
            ISSUEKV(kt + 2, nbuf);

            const u32 kbase = sb + buf * ABUF;

            float s[8][4];
            #pragma unroll
            for (int nt = 0; nt < 8; nt++)
                #pragma unroll
                for (int e = 0; e < 4; e++) s[nt][e] = 0.0f;

            #pragma unroll
            for (int kk = 0; kk < 4; kk++) {
                #pragma unroll
                for (int p = 0; p < 4; p++) {
                    u32 kh[4];
                    u32 baddr = kbase + (p * 16 + brow) * APITCH + kaddB + kk * 32;
                    ldsm4(kh, baddr);
                    int nt0 = 2 * p;
                    mma16816f(s[nt0], qh[kk], &kh[0]);
                    mma16816f(s[nt0 + 1], qh[kk], &kh[2]);
                }
            }

            if (kt >= 2 * qt) {
                int kc0 = kt * 64;
                #pragma unroll
                for (int nt = 0; nt < 8; nt++) {
                    int c = kc0 + nt * 8 + colq;
                    if (c     > rowg0) s[nt][0] = -30000.0f;
                    if (c + 1 > rowg0) s[nt][1] = -30000.0f;
                    if (c     > rowg1) s[nt][2] = -30000.0f;
                    if (c + 1 > rowg1) s[nt][3] = -30000.0f;
                }
            }

            #pragma unroll
            for (int kk = 0; kk < 4; kk++) {
                u32 ph[4];
                ph[0] = packf16(ex2(s[2*kk][0]),   ex2(s[2*kk][1]));
                ph[1] = packf16(ex2(s[2*kk][2]),   ex2(s[2*kk][3]));
                ph[2] = packf16(ex2(s[2*kk+1][0]), ex2(s[2*kk+1][1]));
                ph[3] = packf16(ex2(s[2*kk+1][2]), ex2(s[2*kk+1][3]));
                mma16816f(acc_l, ph, ones2);
                #pragma unroll
                for (int pp = 0; pp < 4; pp++) {
                    u32 vh[4];
                    u32 vaddr = kbase + ATILE + (kk * 16 + vtr) * APITCH
                                + (pp * 16 + vtc) * 2;
                    ldsm4t(vh, vaddr);
                    int nt0 = 2 * pp;
                    mma16816f(o[nt0], ph, &vh[0]);
                    mma16816f(o[nt0 + 1], ph, &vh[2]);
                }
            }

            buf = (buf == 2) ? 0 : buf + 1;
            nbuf = (nbuf == 2) ? 0 : nbuf + 1;
        }
        #undef ISSUEKV

        float il0 = 1.0f / acc_l[0];
        float il1 = 1.0f / acc_l[2];
        #pragma unroll
        for (int nt = 0; nt < 8; nt++) {
            int col = h * HD + nt * 8 + colq;
            size_t o0 = ((size_t)b * TT + rowg0) * DD + col;
            size_t o1 = ((size_t)b * TT + rowg1) * DD + col;
            *(u32*)(g_Cf + o0) = packf16(o[nt][0] * il0, o[nt][1] * il0);
            *(u32*)(g_Cf + o1) = packf16(o[nt][2] * il1, o[nt][3] * il1);
        }

        asm volatile("cp.async.wait_group 0;" ::: "memory");
        __syncthreads();
    }
}

// ---------------- launch -------------------------------------------------------------
extern "C" void kernel_launch(void* const* d_in, const int* in_sizes, int n_in,
                              void* d_out, int out_size)
{
    const float* x  = (const float*)d_in[0];
    const float* Wq = (const float*)d_in[2];
    const float* bq = (const float*)d_in[3];
    const float* Wk = (const float*)d_in[4];
    const float* bk = (const float*)d_in[5];
    const float* Wv = (const float*)d_in[6];
    const float* bv = (const float*)d_in[7];
    const float* Wo = (const float*)d_in[8];
    const float* bo = (const float*)d_in[9];
    float* out = (float*)d_out;

    cvt_all<<<8448, 256>>>(x, Wq, Wk, Wv, Wo);

    cudaFuncSetAttribute(qkv_mma, cudaFuncAttributeMaxDynamicSharedMemorySize,
                         2 * BUF2);
    cudaFuncSetAttribute(out_mma, cudaFuncAttributeMaxDynamicSharedMemorySize,
                         2 * BUF2);
    cudaFuncSetAttribute(attn_mma, cudaFuncAttributeMaxDynamicSharedMemorySize,
                         ASMEM);

    dim3 qgrid(24, MTOT / 128);
    qkv_mma<<<qgrid, 256, 2 * BUF2>>>(bq, bk, bv);

    dim3 agrid(8, HH, BB);
    attn_mma<<<agrid, 256, ASMEM>>>();

    dim3 ogrid(DD / 128, MTOT / 128);
    out_mma<<<ogrid, 256, 2 * BUF2>>>(bo, out);
}